// round 2
// baseline (speedup 1.0000x reference)
#include <cuda_runtime.h>
#include <cstddef>

#define N_NODES 50000
#define N_EDGES 500000
#define H 128
#define H3 384

// ---------------- scratch (static device allocations, allowed) --------------
__device__ float g_sexp [(size_t)N_NODES * H3];      // 76.8 MB
__device__ float g_dsagg[(size_t)N_NODES * H];       // 25.6 MB
__device__ float g_dvagg[(size_t)N_NODES * 3 * H];   // 76.8 MB
__device__ unsigned int g_count[N_NODES];

// ---------------------------------------------------------------------------
// Kernel 1: s_exp = tanh(s @ W1 + b1) @ W2 + b2       [N, 384]
// Block: 64 rows, 256 threads (16 col-groups x 16 row-groups), 4x8 microtile.
// Shared: sS 64x132 (input tile, reused for h1) + sW 16x128 K-tile.  (<48KB)
// ---------------------------------------------------------------------------
#define BM 64
#define SS_STRIDE 132

__device__ __forceinline__ void microk16(float acc[4][8], const float* sA,
                                         const float* sW, int ry, int cx) {
#pragma unroll
    for (int k = 0; k < 16; k++) {
        float a[4];
#pragma unroll
        for (int i = 0; i < 4; i++)
            a[i] = sA[(ry * 4 + i) * SS_STRIDE + k];
        float4 b0 = *(const float4*)(sW + k * 128 + cx * 8);
        float4 b1 = *(const float4*)(sW + k * 128 + cx * 8 + 4);
        float b[8] = {b0.x, b0.y, b0.z, b0.w, b1.x, b1.y, b1.z, b1.w};
#pragma unroll
        for (int i = 0; i < 4; i++)
#pragma unroll
            for (int j = 0; j < 8; j++)
                acc[i][j] = fmaf(a[i], b[j], acc[i][j]);
    }
}

__global__ __launch_bounds__(256) void embed_kernel(
    const float* __restrict__ s,
    const float* __restrict__ W1, const float* __restrict__ b1,
    const float* __restrict__ W2, const float* __restrict__ b2)
{
    __shared__ float sS[BM * SS_STRIDE];   // 33.8 KB
    __shared__ float sW[16 * 128];         //  8.0 KB

    const int t  = threadIdx.x;
    const int r0 = blockIdx.x * BM;
    const int cx = t & 15;     // col group: cols cx*8 .. cx*8+7
    const int ry = t >> 4;     // row group: rows ry*4 .. ry*4+3

    // ---- load s tile [64 x 128] (guarded, zero pad) ----
#pragma unroll
    for (int i = 0; i < 8; i++) {
        int idx4 = t + i * 256;            // 0..2047 float4s
        int row  = idx4 >> 5;              // 32 float4 per row
        int c4   = (idx4 & 31) * 4;
        float4 val = make_float4(0.f, 0.f, 0.f, 0.f);
        if (r0 + row < N_NODES)
            val = *(const float4*)(s + (size_t)(r0 + row) * H + c4);
        *(float4*)(sS + row * SS_STRIDE + c4) = val;
    }
    __syncthreads();

    // ---- phase 1: h1 = tanh(s @ W1 + b1) ----
    float acc[4][8];
#pragma unroll
    for (int i = 0; i < 4; i++)
#pragma unroll
        for (int j = 0; j < 8; j++) acc[i][j] = 0.f;

    for (int kt = 0; kt < 8; kt++) {
        // load full 16x128 K-tile of W1 (2048 floats = 8 x 256 threads)
#pragma unroll
        for (int i = 0; i < 8; i++) {
            int idx = t + i * 256;
            int r = idx >> 7, c = idx & 127;
            sW[idx] = W1[(size_t)(kt * 16 + r) * H + c];
        }
        __syncthreads();
        microk16(acc, sS + kt * 16, sW, ry, cx);
        __syncthreads();
    }

    // write h1 back into sS (all reads of sS are done: synced above)
#pragma unroll
    for (int i = 0; i < 4; i++) {
        int row = ry * 4 + i;
#pragma unroll
        for (int j = 0; j < 8; j++) {
            int col = cx * 8 + j;
            sS[row * SS_STRIDE + col] = tanhf(acc[i][j] + __ldg(b1 + col));
        }
    }
    __syncthreads();

    // ---- phase 2: s_exp = h1 @ W2 + b2, in 3 chunks of 128 cols ----
    for (int chunk = 0; chunk < 3; chunk++) {
        float acc2[4][8];
#pragma unroll
        for (int i = 0; i < 4; i++)
#pragma unroll
            for (int j = 0; j < 8; j++) acc2[i][j] = 0.f;

        for (int kt = 0; kt < 8; kt++) {
            // load full 16x128 K-tile of W2 chunk (2048 floats)
#pragma unroll
            for (int i = 0; i < 8; i++) {
                int idx = t + i * 256;
                int r = idx >> 7, c = idx & 127;
                sW[idx] = W2[(size_t)(kt * 16 + r) * H3 + chunk * 128 + c];
            }
            __syncthreads();
            microk16(acc2, sS + kt * 16, sW, ry, cx);
            __syncthreads();
        }

#pragma unroll
        for (int i = 0; i < 4; i++) {
            int row = r0 + ry * 4 + i;
            if (row < N_NODES) {
#pragma unroll
                for (int j = 0; j < 8; j++) {
                    int col = chunk * 128 + cx * 8 + j;
                    g_sexp[(size_t)row * H3 + col] = acc2[i][j] + __ldg(b2 + col);
                }
            }
        }
    }
}

// ---------------------------------------------------------------------------
// Kernel 2: per-edge gather/compute/scatter. One warp per edge; lane l owns
// 4 consecutive h-columns (float4). Vector reductions (red.global.add.v4.f32).
// ---------------------------------------------------------------------------
__device__ __forceinline__ void red_add_v4(float* addr, float x, float y,
                                           float z, float w) {
    asm volatile("red.global.add.v4.f32 [%0], {%1,%2,%3,%4};"
                 :: "l"(addr), "f"(x), "f"(y), "f"(z), "f"(w) : "memory");
}

__global__ __launch_bounds__(256) void edge_kernel(
    const int*   __restrict__ ei,
    const float* __restrict__ dij,
    const float* __restrict__ dir,
    const float* __restrict__ v,
    const float* __restrict__ Wd,
    const float* __restrict__ bd)
{
    __shared__ float sWd[H3], sbd[H3];
    for (int i = threadIdx.x; i < H3; i += 256) { sWd[i] = Wd[i]; sbd[i] = bd[i]; }
    __syncthreads();

    const int e = (int)((blockIdx.x * 256u + threadIdx.x) >> 5);
    if (e >= N_EDGES) return;
    const int lane = threadIdx.x & 31;

    const int src = __ldg(ei + e);
    const int dst = __ldg(ei + N_EDGES + e);
    const float d  = __ldg(dij + e);
    const float dr0 = __ldg(dir + 3 * e);
    const float dr1 = __ldg(dir + 3 * e + 1);
    const float dr2 = __ldg(dir + 3 * e + 2);

    const int c = lane * 4;
    const float4* sx = (const float4*)(g_sexp + (size_t)src * H3);
    float4 ev = __ldg(sx + lane);        // dv_v slot  (cols 0..127)
    float4 es = __ldg(sx + 32 + lane);   // ds slot    (cols 128..255)
    float4 er = __ldg(sx + 64 + lane);   // dvr slot   (cols 256..383)

    float4 wv = ((const float4*)sWd)[lane];
    float4 bv = ((const float4*)sbd)[lane];
    float4 ws = ((const float4*)sWd)[32 + lane];
    float4 bs = ((const float4*)sbd)[32 + lane];
    float4 wr = ((const float4*)sWd)[64 + lane];
    float4 br = ((const float4*)sbd)[64 + lane];

    float4 gv, gs, gr;
    gv.x = ev.x * fmaf(d, wv.x, bv.x); gv.y = ev.y * fmaf(d, wv.y, bv.y);
    gv.z = ev.z * fmaf(d, wv.z, bv.z); gv.w = ev.w * fmaf(d, wv.w, bv.w);
    gs.x = es.x * fmaf(d, ws.x, bs.x); gs.y = es.y * fmaf(d, ws.y, bs.y);
    gs.z = es.z * fmaf(d, ws.z, bs.z); gs.w = es.w * fmaf(d, ws.w, bs.w);
    gr.x = er.x * fmaf(d, wr.x, br.x); gr.y = er.y * fmaf(d, wr.y, br.y);
    gr.z = er.z * fmaf(d, wr.z, br.z); gr.w = er.w * fmaf(d, wr.w, br.w);

    // ds scatter
    red_add_v4(g_dsagg + (size_t)dst * H + c, gs.x, gs.y, gs.z, gs.w);

    // dv scatter: dv[a,k] = dvr[k]*dir[a] + dv_v[k]*v[src,a,k]
    const float4* vv = (const float4*)(v + (size_t)src * 3 * H);
    const float dira[3] = {dr0, dr1, dr2};
#pragma unroll
    for (int a = 0; a < 3; a++) {
        float4 vx = __ldg(vv + a * 32 + lane);
        float da = dira[a];
        float4 m;
        m.x = fmaf(gr.x, da, gv.x * vx.x);
        m.y = fmaf(gr.y, da, gv.y * vx.y);
        m.z = fmaf(gr.z, da, gv.z * vx.z);
        m.w = fmaf(gr.w, da, gv.w * vx.w);
        red_add_v4(g_dvagg + (size_t)dst * 3 * H + a * H + c, m.x, m.y, m.z, m.w);
    }

    if (lane == 0) atomicAdd(&g_count[dst], 1u);
}

// ---------------------------------------------------------------------------
// Kernel 3: finalize. One block per node, 128 threads = 128 float4 per node
// (96 for v part, 32 for s part).  out = [v+dv_agg/denom (N*384) | s+ds_agg/denom (N*128)]
// ---------------------------------------------------------------------------
__global__ __launch_bounds__(128) void finalize_kernel(
    const float* __restrict__ v,
    const float* __restrict__ s,
    float* __restrict__ out)
{
    const int node = blockIdx.x;
    const int t = threadIdx.x;
    const float cnt = (float)g_count[node];
    const float inv = 1.0f / fmaxf(cnt, 1.0f);

    if (t < 96) {
        size_t i4 = (size_t)node * 96 + t;
        float4 a = ((const float4*)v)[i4];
        float4 b = ((const float4*)g_dvagg)[i4];
        float4 o = make_float4(fmaf(b.x, inv, a.x), fmaf(b.y, inv, a.y),
                               fmaf(b.z, inv, a.z), fmaf(b.w, inv, a.w));
        ((float4*)out)[i4] = o;
    } else {
        int u = t - 96;
        size_t i4 = (size_t)node * 32 + u;
        float4 a = ((const float4*)s)[i4];
        float4 b = ((const float4*)g_dsagg)[i4];
        float4 o = make_float4(fmaf(b.x, inv, a.x), fmaf(b.y, inv, a.y),
                               fmaf(b.z, inv, a.z), fmaf(b.w, inv, a.w));
        ((float4*)(out + (size_t)N_NODES * 3 * H))[i4] = o;
    }
}

// ---------------------------------------------------------------------------
extern "C" void kernel_launch(void* const* d_in, const int* in_sizes, int n_in,
                              void* d_out, int out_size) {
    const float* v   = (const float*)d_in[0];
    const float* s   = (const float*)d_in[1];
    const int*   ei  = (const int*)  d_in[2];
    const float* dij = (const float*)d_in[3];
    const float* dir = (const float*)d_in[4];
    const float* W1  = (const float*)d_in[5];
    const float* b1  = (const float*)d_in[6];
    const float* W2  = (const float*)d_in[7];
    const float* b2  = (const float*)d_in[8];
    const float* Wd  = (const float*)d_in[9];
    const float* bd  = (const float*)d_in[10];
    float* out = (float*)d_out;

    void *pds, *pdv, *pcnt;
    cudaGetSymbolAddress(&pds,  g_dsagg);
    cudaGetSymbolAddress(&pdv,  g_dvagg);
    cudaGetSymbolAddress(&pcnt, g_count);
    cudaMemsetAsync(pds,  0, sizeof(float) * (size_t)N_NODES * H, 0);
    cudaMemsetAsync(pdv,  0, sizeof(float) * (size_t)N_NODES * 3 * H, 0);
    cudaMemsetAsync(pcnt, 0, sizeof(unsigned int) * (size_t)N_NODES, 0);

    embed_kernel<<<(N_NODES + BM - 1) / BM, 256>>>(s, W1, b1, W2, b2);
    edge_kernel<<<(N_EDGES * 32 + 255) / 256, 256>>>(ei, dij, dir, v, Wd, bd);
    finalize_kernel<<<N_NODES, 128>>>(v, s, out);
}

// round 3
// speedup vs baseline: 1.0593x; 1.0593x over previous
#include <cuda_runtime.h>
#include <cstddef>

#define N_NODES 50000
#define N_EDGES 500000
#define H 128
#define H3 384

// ---------------- scratch (static device allocations, allowed) --------------
__device__ float g_sexp [(size_t)N_NODES * H3];      // 76.8 MB
__device__ int   g_count[N_NODES];                   // per-dst degree
__device__ int   g_fill [N_NODES];                   // bucket cursors
__device__ int   g_start[N_NODES + 1];               // CSR row offsets
__device__ int   g_bucket[N_EDGES];                  // edge ids grouped by dst

// ---------------------------------------------------------------------------
// Kernel 1: s_exp = tanh(s @ W1 + b1) @ W2 + b2       [N, 384]
// Block: 64 rows, 256 threads, 4x8 microtile. Dynamic smem:
//   sS: 64 x 132 fp32 (input tile, reused for h1)   33.8 KB
//   sW: 64 x 128 fp32 (K-tile of weights)           32.8 KB
// K processed in 2 tiles of 64 -> few __syncthreads().
// ---------------------------------------------------------------------------
#define BM 64
#define SS_STRIDE 132
#define SMEM_EMBED_BYTES ((BM * SS_STRIDE + 64 * 128) * 4)

__device__ __forceinline__ void microk64(float acc[4][8], const float* sA,
                                         const float* sW, int ry, int cx) {
#pragma unroll 8
    for (int k = 0; k < 64; k++) {
        float a[4];
#pragma unroll
        for (int i = 0; i < 4; i++)
            a[i] = sA[(ry * 4 + i) * SS_STRIDE + k];
        float4 b0 = *(const float4*)(sW + k * 128 + cx * 8);
        float4 b1 = *(const float4*)(sW + k * 128 + cx * 8 + 4);
        float b[8] = {b0.x, b0.y, b0.z, b0.w, b1.x, b1.y, b1.z, b1.w};
#pragma unroll
        for (int i = 0; i < 4; i++)
#pragma unroll
            for (int j = 0; j < 8; j++)
                acc[i][j] = fmaf(a[i], b[j], acc[i][j]);
    }
}

__device__ __forceinline__ void load_wtile(float* sW, const float* W,
                                           int kbase, int ldw, int cbase, int t) {
#pragma unroll
    for (int i = 0; i < 8; i++) {
        int idx4 = t + i * 256;          // 0..2047 float4s
        int r  = idx4 >> 5;              // 32 float4 per 128-col row
        int c4 = (idx4 & 31) * 4;
        *(float4*)(sW + r * 128 + c4) =
            *(const float4*)(W + (size_t)(kbase + r) * ldw + cbase + c4);
    }
}

__global__ __launch_bounds__(256) void embed_kernel(
    const float* __restrict__ s,
    const float* __restrict__ W1, const float* __restrict__ b1,
    const float* __restrict__ W2, const float* __restrict__ b2)
{
    extern __shared__ float smem[];
    float* sS = smem;                  // BM x SS_STRIDE
    float* sW = smem + BM * SS_STRIDE; // 64 x 128

    const int t  = threadIdx.x;
    const int r0 = blockIdx.x * BM;
    const int cx = t & 15;
    const int ry = t >> 4;

    // ---- load s tile [64 x 128] (guarded, zero pad) ----
#pragma unroll
    for (int i = 0; i < 8; i++) {
        int idx4 = t + i * 256;
        int row  = idx4 >> 5;
        int c4   = (idx4 & 31) * 4;
        float4 val = make_float4(0.f, 0.f, 0.f, 0.f);
        if (r0 + row < N_NODES)
            val = *(const float4*)(s + (size_t)(r0 + row) * H + c4);
        *(float4*)(sS + row * SS_STRIDE + c4) = val;
    }

    // ---- phase 1: h1 = tanh(s @ W1 + b1), K in 2 tiles of 64 ----
    float acc[4][8];
#pragma unroll
    for (int i = 0; i < 4; i++)
#pragma unroll
        for (int j = 0; j < 8; j++) acc[i][j] = 0.f;

#pragma unroll
    for (int kt = 0; kt < 2; kt++) {
        __syncthreads();                        // prev compute / sS-load done
        load_wtile(sW, W1, kt * 64, H, 0, t);
        __syncthreads();
        microk64(acc, sS + kt * 64, sW, ry, cx);
    }

    __syncthreads();
    // write h1 back into sS
#pragma unroll
    for (int i = 0; i < 4; i++) {
        int row = ry * 4 + i;
#pragma unroll
        for (int j = 0; j < 8; j++) {
            int col = cx * 8 + j;
            sS[row * SS_STRIDE + col] = tanhf(acc[i][j] + __ldg(b1 + col));
        }
    }

    // ---- phase 2: s_exp = h1 @ W2 + b2, 3 chunks of 128 cols ----
    for (int chunk = 0; chunk < 3; chunk++) {
        float acc2[4][8];
#pragma unroll
        for (int i = 0; i < 4; i++)
#pragma unroll
            for (int j = 0; j < 8; j++) acc2[i][j] = 0.f;

#pragma unroll
        for (int kt = 0; kt < 2; kt++) {
            __syncthreads();
            load_wtile(sW, W2, kt * 64, H3, chunk * 128, t);
            __syncthreads();
            microk64(acc2, sS + kt * 64, sW, ry, cx);
        }

#pragma unroll
        for (int i = 0; i < 4; i++) {
            int row = r0 + ry * 4 + i;
            if (row < N_NODES) {
#pragma unroll
                for (int j = 0; j < 8; j++) {
                    int col = chunk * 128 + cx * 8 + j;
                    g_sexp[(size_t)row * H3 + col] = acc2[i][j] + __ldg(b2 + col);
                }
            }
        }
    }
}

// ---------------------------------------------------------------------------
// CSR build: histogram -> single-block scan -> bucket fill
// ---------------------------------------------------------------------------
__global__ __launch_bounds__(256) void hist_kernel(const int* __restrict__ ei) {
    int i = blockIdx.x * 256 + threadIdx.x;
    if (i < N_EDGES) atomicAdd(&g_count[__ldg(ei + N_EDGES + i)], 1);
}

__global__ __launch_bounds__(1024) void scan_kernel() {
    __shared__ int tmp[1024];
    const int per = (N_NODES + 1023) / 1024;   // 49
    const int t = threadIdx.x;
    const int base = t * per;
    int sum = 0;
    for (int i = 0; i < per; i++) {
        int idx = base + i;
        if (idx < N_NODES) sum += g_count[idx];
    }
    tmp[t] = sum;
    __syncthreads();
    for (int off = 1; off < 1024; off <<= 1) {
        int v = (t >= off) ? tmp[t - off] : 0;
        __syncthreads();
        tmp[t] += v;
        __syncthreads();
    }
    int run = tmp[t] - sum;   // exclusive prefix
    for (int i = 0; i < per; i++) {
        int idx = base + i;
        if (idx < N_NODES) {
            g_start[idx] = run;
            run += g_count[idx];
        }
    }
    if (t == 0) g_start[N_NODES] = N_EDGES;
}

__global__ __launch_bounds__(256) void fill_kernel(const int* __restrict__ ei) {
    int e = blockIdx.x * 256 + threadIdx.x;
    if (e >= N_EDGES) return;
    int dst = __ldg(ei + N_EDGES + e);
    int pos = g_start[dst] + atomicAdd(&g_fill[dst], 1);
    g_bucket[pos] = e;
}

// ---------------------------------------------------------------------------
// Kernel 2: gather + finalize. One block (128 threads) per dst node.
// Thread t owns column t. Accumulates ds + dv[3] in registers, writes output
// directly:  out = [v + dv_agg/denom (N*384) | s + ds_agg/denom (N*128)]
// ---------------------------------------------------------------------------
__global__ __launch_bounds__(128) void gather_kernel(
    const float* __restrict__ v,
    const float* __restrict__ s,
    const int*   __restrict__ ei,
    const float* __restrict__ dij,
    const float* __restrict__ dir,
    const float* __restrict__ Wd,
    const float* __restrict__ bd,
    float* __restrict__ out)
{
    const int node = blockIdx.x;
    const int t = threadIdx.x;

    const int beg = g_start[node];
    const int end = g_start[node + 1];

    const float wv = __ldg(Wd + t),       bv = __ldg(bd + t);
    const float ws = __ldg(Wd + 128 + t), bs = __ldg(bd + 128 + t);
    const float wr = __ldg(Wd + 256 + t), br = __ldg(bd + 256 + t);

    float accs = 0.f, acc0 = 0.f, acc1 = 0.f, acc2 = 0.f;

    for (int j = beg; j < end; j++) {
        const int e   = __ldg(g_bucket + j);
        const int src = __ldg(ei + e);
        const float d  = __ldg(dij + e);
        const float d0 = __ldg(dir + 3 * e);
        const float d1 = __ldg(dir + 3 * e + 1);
        const float d2 = __ldg(dir + 3 * e + 2);

        const float* sx = g_sexp + (size_t)src * H3;
        const float ev = __ldg(sx + t);
        const float es = __ldg(sx + 128 + t);
        const float er = __ldg(sx + 256 + t);

        const float gv = ev * fmaf(d, wv, bv);
        const float gs = es * fmaf(d, ws, bs);
        const float gr = er * fmaf(d, wr, br);

        accs += gs;

        const float* vb = v + (size_t)src * H3;
        acc0 = fmaf(gr, d0, fmaf(gv, __ldg(vb + t),        acc0));
        acc1 = fmaf(gr, d1, fmaf(gv, __ldg(vb + 128 + t),  acc1));
        acc2 = fmaf(gr, d2, fmaf(gv, __ldg(vb + 256 + t),  acc2));
    }

    const float inv = 1.0f / fmaxf((float)(end - beg), 1.0f);

    const size_t vb = (size_t)node * H3;
    out[vb + t]       = __ldg(v + vb + t)       + acc0 * inv;
    out[vb + 128 + t] = __ldg(v + vb + 128 + t) + acc1 * inv;
    out[vb + 256 + t] = __ldg(v + vb + 256 + t) + acc2 * inv;
    out[(size_t)N_NODES * H3 + (size_t)node * H + t] =
        __ldg(s + (size_t)node * H + t) + accs * inv;
}

// ---------------------------------------------------------------------------
extern "C" void kernel_launch(void* const* d_in, const int* in_sizes, int n_in,
                              void* d_out, int out_size) {
    const float* v   = (const float*)d_in[0];
    const float* s   = (const float*)d_in[1];
    const int*   ei  = (const int*)  d_in[2];
    const float* dij = (const float*)d_in[3];
    const float* dir = (const float*)d_in[4];
    const float* W1  = (const float*)d_in[5];
    const float* b1  = (const float*)d_in[6];
    const float* W2  = (const float*)d_in[7];
    const float* b2  = (const float*)d_in[8];
    const float* Wd  = (const float*)d_in[9];
    const float* bd  = (const float*)d_in[10];
    float* out = (float*)d_out;

    cudaFuncSetAttribute(embed_kernel,
                         cudaFuncAttributeMaxDynamicSharedMemorySize,
                         SMEM_EMBED_BYTES);

    void *pcnt, *pfill;
    cudaGetSymbolAddress(&pcnt,  g_count);
    cudaGetSymbolAddress(&pfill, g_fill);
    cudaMemsetAsync(pcnt,  0, sizeof(int) * N_NODES, 0);
    cudaMemsetAsync(pfill, 0, sizeof(int) * N_NODES, 0);

    embed_kernel<<<(N_NODES + BM - 1) / BM, 256, SMEM_EMBED_BYTES>>>(
        s, W1, b1, W2, b2);
    hist_kernel<<<(N_EDGES + 255) / 256, 256>>>(ei);
    scan_kernel<<<1, 1024>>>();
    fill_kernel<<<(N_EDGES + 255) / 256, 256>>>(ei);
    gather_kernel<<<N_NODES, 128>>>(v, s, ei, dij, dir, Wd, bd, out);
}

// round 4
// speedup vs baseline: 1.5646x; 1.4770x over previous
#include <cuda_runtime.h>
#include <cstdint>
#include <cstddef>

#define N_NODES 50000
#define N_EDGES 500000
#define H 128
#define H3 384

// ---------------- scratch (static device allocations, allowed) --------------
__device__ float g_sexp [(size_t)N_NODES * H3];      // 76.8 MB
__device__ int   g_count[N_NODES];                   // per-dst degree
__device__ int   g_fill [N_NODES];                   // bucket cursors
__device__ int   g_start[N_NODES + 1];               // CSR row offsets
__device__ int   g_bucket[N_EDGES];                  // edge ids grouped by dst

// ---------------------------------------------------------------------------
// tf32 helpers (mma.sync m16n8k8, fp32 accumulate)
// ---------------------------------------------------------------------------
__device__ __forceinline__ uint32_t f2tf(float f) {
    uint32_t u;
    asm("cvt.rna.tf32.f32 %0, %1;" : "=r"(u) : "f"(f));
    return u;
}

__device__ __forceinline__ void mma_tf32(float c[4],
                                         uint32_t a0, uint32_t a1,
                                         uint32_t a2, uint32_t a3,
                                         uint32_t b0, uint32_t b1) {
    asm volatile(
        "mma.sync.aligned.m16n8k8.row.col.f32.tf32.tf32.f32 "
        "{%0,%1,%2,%3}, {%4,%5,%6,%7}, {%8,%9}, {%0,%1,%2,%3};"
        : "+f"(c[0]), "+f"(c[1]), "+f"(c[2]), "+f"(c[3])
        : "r"(a0), "r"(a1), "r"(a2), "r"(a3), "r"(b0), "r"(b1));
}

// ---------------------------------------------------------------------------
// Kernel 1: s_exp = tanh(s @ W1 + b1) @ W2 + b2       [N, 384]
// Block: 128 rows, 256 threads (8 warps: wm 0..1 x wn 0..3).
// Each warp: 64 rows x 32 cols via 4x4 m16n8k8 tf32 mma tiles.
// smem (dynamic, 135 KB): sS 128xSTR tf32 (input tile / h1), sW 128xSTR tf32.
// ---------------------------------------------------------------------------
#define BM 128
#define STR 132
#define SMEM_EMBED_BYTES (2 * 128 * STR * 4)

__device__ __forceinline__ void compute_mma(float acc[4][4][4],
                                            const uint32_t* __restrict__ sA,
                                            const uint32_t* __restrict__ sW,
                                            int wm, int wn, int gid, int tig) {
#pragma unroll
    for (int k = 0; k < 128; k += 8) {
        uint32_t a[4][4];
#pragma unroll
        for (int mt = 0; mt < 4; mt++) {
            int r = wm * 64 + mt * 16 + gid;
            a[mt][0] = sA[r * STR + k + tig];
            a[mt][1] = sA[(r + 8) * STR + k + tig];
            a[mt][2] = sA[r * STR + k + tig + 4];
            a[mt][3] = sA[(r + 8) * STR + k + tig + 4];
        }
#pragma unroll
        for (int nt = 0; nt < 4; nt++) {
            int ncol = wn * 32 + nt * 8 + gid;
            uint32_t b0 = sW[(k + tig) * STR + ncol];
            uint32_t b1 = sW[(k + tig + 4) * STR + ncol];
#pragma unroll
            for (int mt = 0; mt < 4; mt++)
                mma_tf32(acc[mt][nt], a[mt][0], a[mt][1], a[mt][2], a[mt][3],
                         b0, b1);
        }
    }
}

__global__ __launch_bounds__(256) void embed_kernel(
    const float* __restrict__ s,
    const float* __restrict__ W1, const float* __restrict__ b1,
    const float* __restrict__ W2, const float* __restrict__ b2)
{
    extern __shared__ uint32_t smem_u[];
    uint32_t* sS = smem_u;               // 128 x STR (tf32)
    uint32_t* sW = smem_u + 128 * STR;   // 128 x STR (tf32)

    const int t    = threadIdx.x;
    const int r0   = blockIdx.x * BM;
    const int wid  = t >> 5, lane = t & 31;
    const int wm   = wid & 1, wn = wid >> 1;
    const int gid  = lane >> 2, tig = lane & 3;

    // ---- load s tile [128 x 128] (guarded), convert to tf32 ----
#pragma unroll
    for (int i = 0; i < 16; i++) {
        int idx4 = t + i * 256;              // 0..4095 float4s
        int row  = idx4 >> 5;                // 32 float4 per row
        int c4   = (idx4 & 31) * 4;
        float4 val = make_float4(0.f, 0.f, 0.f, 0.f);
        if (r0 + row < N_NODES)
            val = *(const float4*)(s + (size_t)(r0 + row) * H + c4);
        uint32_t* p = sS + row * STR + c4;
        p[0] = f2tf(val.x); p[1] = f2tf(val.y);
        p[2] = f2tf(val.z); p[3] = f2tf(val.w);
    }
    // ---- load W1 [128 x 128] ----
#pragma unroll
    for (int i = 0; i < 16; i++) {
        int idx4 = t + i * 256;
        int row  = idx4 >> 5;
        int c4   = (idx4 & 31) * 4;
        float4 val = *(const float4*)(W1 + (size_t)row * H + c4);
        uint32_t* p = sW + row * STR + c4;
        p[0] = f2tf(val.x); p[1] = f2tf(val.y);
        p[2] = f2tf(val.z); p[3] = f2tf(val.w);
    }
    __syncthreads();

    // ---- phase 1: acc = s @ W1 ----
    float acc[4][4][4];
#pragma unroll
    for (int mt = 0; mt < 4; mt++)
#pragma unroll
        for (int nt = 0; nt < 4; nt++)
#pragma unroll
            for (int i = 0; i < 4; i++) acc[mt][nt][i] = 0.f;

    compute_mma(acc, sS, sW, wm, wn, gid, tig);
    __syncthreads();   // all warps done reading sS before h1 overwrite

    // ---- h1 = tanh(acc + b1) back into sS as tf32 ----
#pragma unroll
    for (int mt = 0; mt < 4; mt++) {
        int row = wm * 64 + mt * 16 + gid;
#pragma unroll
        for (int nt = 0; nt < 4; nt++) {
            int col = wn * 32 + nt * 8 + tig * 2;
            float ba = __ldg(b1 + col), bb = __ldg(b1 + col + 1);
            sS[row * STR + col]           = f2tf(tanhf(acc[mt][nt][0] + ba));
            sS[row * STR + col + 1]       = f2tf(tanhf(acc[mt][nt][1] + bb));
            sS[(row + 8) * STR + col]     = f2tf(tanhf(acc[mt][nt][2] + ba));
            sS[(row + 8) * STR + col + 1] = f2tf(tanhf(acc[mt][nt][3] + bb));
        }
    }

    // ---- phase 2: s_exp = h1 @ W2 + b2, 3 chunks of 128 cols ----
    for (int chunk = 0; chunk < 3; chunk++) {
        __syncthreads();   // h1 writes done / previous sW reads done
#pragma unroll
        for (int i = 0; i < 16; i++) {
            int idx4 = t + i * 256;
            int row  = idx4 >> 5;
            int c4   = (idx4 & 31) * 4;
            float4 val = *(const float4*)(W2 + (size_t)row * H3
                                          + chunk * 128 + c4);
            uint32_t* p = sW + row * STR + c4;
            p[0] = f2tf(val.x); p[1] = f2tf(val.y);
            p[2] = f2tf(val.z); p[3] = f2tf(val.w);
        }
        __syncthreads();

        float acc2[4][4][4];
#pragma unroll
        for (int mt = 0; mt < 4; mt++)
#pragma unroll
            for (int nt = 0; nt < 4; nt++)
#pragma unroll
                for (int i = 0; i < 4; i++) acc2[mt][nt][i] = 0.f;

        compute_mma(acc2, sS, sW, wm, wn, gid, tig);

        // write out (fp32)
#pragma unroll
        for (int mt = 0; mt < 4; mt++) {
            int rl = wm * 64 + mt * 16 + gid;
#pragma unroll
            for (int nt = 0; nt < 4; nt++) {
                int col = chunk * 128 + wn * 32 + nt * 8 + tig * 2;
                float ba = __ldg(b2 + col), bb = __ldg(b2 + col + 1);
                int row = r0 + rl;
                if (row < N_NODES) {
                    float2 o = make_float2(acc2[mt][nt][0] + ba,
                                           acc2[mt][nt][1] + bb);
                    *(float2*)(g_sexp + (size_t)row * H3 + col) = o;
                }
                if (row + 8 < N_NODES) {
                    float2 o = make_float2(acc2[mt][nt][2] + ba,
                                           acc2[mt][nt][3] + bb);
                    *(float2*)(g_sexp + (size_t)(row + 8) * H3 + col) = o;
                }
            }
        }
    }
}

// ---------------------------------------------------------------------------
// CSR build: histogram -> single-block scan -> bucket fill
// ---------------------------------------------------------------------------
__global__ __launch_bounds__(256) void hist_kernel(const int* __restrict__ ei) {
    int i = blockIdx.x * 256 + threadIdx.x;
    if (i < N_EDGES) atomicAdd(&g_count[__ldg(ei + N_EDGES + i)], 1);
}

__global__ __launch_bounds__(1024) void scan_kernel() {
    __shared__ int tmp[1024];
    const int per = (N_NODES + 1023) / 1024;   // 49
    const int t = threadIdx.x;
    const int base = t * per;
    int sum = 0;
    for (int i = 0; i < per; i++) {
        int idx = base + i;
        if (idx < N_NODES) sum += g_count[idx];
    }
    tmp[t] = sum;
    __syncthreads();
    for (int off = 1; off < 1024; off <<= 1) {
        int v = (t >= off) ? tmp[t - off] : 0;
        __syncthreads();
        tmp[t] += v;
        __syncthreads();
    }
    int run = tmp[t] - sum;   // exclusive prefix
    for (int i = 0; i < per; i++) {
        int idx = base + i;
        if (idx < N_NODES) {
            g_start[idx] = run;
            run += g_count[idx];
        }
    }
    if (t == 0) g_start[N_NODES] = N_EDGES;
}

__global__ __launch_bounds__(256) void fill_kernel(const int* __restrict__ ei) {
    int e = blockIdx.x * 256 + threadIdx.x;
    if (e >= N_EDGES) return;
    int dst = __ldg(ei + N_EDGES + e);
    int pos = g_start[dst] + atomicAdd(&g_fill[dst], 1);
    g_bucket[pos] = e;
}

// ---------------------------------------------------------------------------
// Kernel 2: gather + finalize. One block (128 threads) per dst node.
// Thread t owns column t. Accumulates ds + dv[3] in registers, writes output
// directly:  out = [v + dv_agg/denom (N*384) | s + ds_agg/denom (N*128)]
// ---------------------------------------------------------------------------
__global__ __launch_bounds__(128) void gather_kernel(
    const float* __restrict__ v,
    const float* __restrict__ s,
    const int*   __restrict__ ei,
    const float* __restrict__ dij,
    const float* __restrict__ dir,
    const float* __restrict__ Wd,
    const float* __restrict__ bd,
    float* __restrict__ out)
{
    const int node = blockIdx.x;
    const int t = threadIdx.x;

    const int beg = g_start[node];
    const int end = g_start[node + 1];

    const float wv = __ldg(Wd + t),       bv = __ldg(bd + t);
    const float ws = __ldg(Wd + 128 + t), bs = __ldg(bd + 128 + t);
    const float wr = __ldg(Wd + 256 + t), br = __ldg(bd + 256 + t);

    float accs = 0.f, acc0 = 0.f, acc1 = 0.f, acc2 = 0.f;

#pragma unroll 4
    for (int j = beg; j < end; j++) {
        const int e   = __ldg(g_bucket + j);
        const int src = __ldg(ei + e);
        const float d  = __ldg(dij + e);
        const float d0 = __ldg(dir + 3 * e);
        const float d1 = __ldg(dir + 3 * e + 1);
        const float d2 = __ldg(dir + 3 * e + 2);

        const float* sx = g_sexp + (size_t)src * H3;
        const float ev = __ldg(sx + t);
        const float es = __ldg(sx + 128 + t);
        const float er = __ldg(sx + 256 + t);

        const float gv = ev * fmaf(d, wv, bv);
        const float gs = es * fmaf(d, ws, bs);
        const float gr = er * fmaf(d, wr, br);

        accs += gs;

        const float* vb = v + (size_t)src * H3;
        acc0 = fmaf(gr, d0, fmaf(gv, __ldg(vb + t),        acc0));
        acc1 = fmaf(gr, d1, fmaf(gv, __ldg(vb + 128 + t),  acc1));
        acc2 = fmaf(gr, d2, fmaf(gv, __ldg(vb + 256 + t),  acc2));
    }

    const float inv = 1.0f / fmaxf((float)(end - beg), 1.0f);

    const size_t vb = (size_t)node * H3;
    out[vb + t]       = __ldg(v + vb + t)       + acc0 * inv;
    out[vb + 128 + t] = __ldg(v + vb + 128 + t) + acc1 * inv;
    out[vb + 256 + t] = __ldg(v + vb + 256 + t) + acc2 * inv;
    out[(size_t)N_NODES * H3 + (size_t)node * H + t] =
        __ldg(s + (size_t)node * H + t) + accs * inv;
}

// ---------------------------------------------------------------------------
extern "C" void kernel_launch(void* const* d_in, const int* in_sizes, int n_in,
                              void* d_out, int out_size) {
    const float* v   = (const float*)d_in[0];
    const float* s   = (const float*)d_in[1];
    const int*   ei  = (const int*)  d_in[2];
    const float* dij = (const float*)d_in[3];
    const float* dir = (const float*)d_in[4];
    const float* W1  = (const float*)d_in[5];
    const float* b1  = (const float*)d_in[6];
    const float* W2  = (const float*)d_in[7];
    const float* b2  = (const float*)d_in[8];
    const float* Wd  = (const float*)d_in[9];
    const float* bd  = (const float*)d_in[10];
    float* out = (float*)d_out;

    cudaFuncSetAttribute(embed_kernel,
                         cudaFuncAttributeMaxDynamicSharedMemorySize,
                         SMEM_EMBED_BYTES);

    void *pcnt, *pfill;
    cudaGetSymbolAddress(&pcnt,  g_count);
    cudaGetSymbolAddress(&pfill, g_fill);
    cudaMemsetAsync(pcnt,  0, sizeof(int) * N_NODES, 0);
    cudaMemsetAsync(pfill, 0, sizeof(int) * N_NODES, 0);

    embed_kernel<<<(N_NODES + BM - 1) / BM, 256, SMEM_EMBED_BYTES>>>(
        s, W1, b1, W2, b2);
    hist_kernel<<<(N_EDGES + 255) / 256, 256>>>(ei);
    scan_kernel<<<1, 1024>>>();
    fill_kernel<<<(N_EDGES + 255) / 256, 256>>>(ei);
    gather_kernel<<<N_NODES, 128>>>(v, s, ei, dij, dir, Wd, bd, out);
}

// round 5
// speedup vs baseline: 2.3250x; 1.4860x over previous
#include <cuda_runtime.h>
#include <cuda_fp16.h>
#include <cstdint>
#include <cstddef>

#define N_NODES 50000
#define N_EDGES 500000
#define H 128
#define H3 384

// ---------------- scratch (static device allocations, allowed) --------------
__device__ __half2 g_sexp16[(size_t)N_NODES * H3 / 2];  // 38.4 MB
__device__ __half2 g_v16  [(size_t)N_NODES * H3 / 2];   // 38.4 MB
__device__ int    g_count[N_NODES];
__device__ int    g_fill [N_NODES];
__device__ int    g_start[N_NODES + 1];
__device__ int    g_bsrc [N_EDGES];                      // src per bucket slot
__device__ float4 g_bdat [N_EDGES];                      // {d, dir0, dir1, dir2}

// ---------------------------------------------------------------------------
// tf32 helpers (mma.sync m16n8k8, fp32 accumulate)
// ---------------------------------------------------------------------------
__device__ __forceinline__ uint32_t f2tf(float f) {
    uint32_t u;
    asm("cvt.rna.tf32.f32 %0, %1;" : "=r"(u) : "f"(f));
    return u;
}

__device__ __forceinline__ void mma_tf32(float c[4],
                                         uint32_t a0, uint32_t a1,
                                         uint32_t a2, uint32_t a3,
                                         uint32_t b0, uint32_t b1) {
    asm volatile(
        "mma.sync.aligned.m16n8k8.row.col.f32.tf32.tf32.f32 "
        "{%0,%1,%2,%3}, {%4,%5,%6,%7}, {%8,%9}, {%0,%1,%2,%3};"
        : "+f"(c[0]), "+f"(c[1]), "+f"(c[2]), "+f"(c[3])
        : "r"(a0), "r"(a1), "r"(a2), "r"(a3), "r"(b0), "r"(b1));
}

// ---------------------------------------------------------------------------
// Kernel 1: s_exp = tanh(s @ W1 + b1) @ W2 + b2   -> fp16 g_sexp16  [N, 384]
// Block: 128 rows, 256 threads (8 warps). Warp: 64x32 via 4x4 m16n8k8 tiles.
// ---------------------------------------------------------------------------
#define BM 128
#define STR 132
#define SMEM_EMBED_BYTES (2 * 128 * STR * 4)

__device__ __forceinline__ void compute_mma(float acc[4][4][4],
                                            const uint32_t* __restrict__ sA,
                                            const uint32_t* __restrict__ sW,
                                            int wm, int wn, int gid, int tig) {
#pragma unroll
    for (int k = 0; k < 128; k += 8) {
        uint32_t a[4][4];
#pragma unroll
        for (int mt = 0; mt < 4; mt++) {
            int r = wm * 64 + mt * 16 + gid;
            a[mt][0] = sA[r * STR + k + tig];
            a[mt][1] = sA[(r + 8) * STR + k + tig];
            a[mt][2] = sA[r * STR + k + tig + 4];
            a[mt][3] = sA[(r + 8) * STR + k + tig + 4];
        }
#pragma unroll
        for (int nt = 0; nt < 4; nt++) {
            int ncol = wn * 32 + nt * 8 + gid;
            uint32_t b0 = sW[(k + tig) * STR + ncol];
            uint32_t b1 = sW[(k + tig + 4) * STR + ncol];
#pragma unroll
            for (int mt = 0; mt < 4; mt++)
                mma_tf32(acc[mt][nt], a[mt][0], a[mt][1], a[mt][2], a[mt][3],
                         b0, b1);
        }
    }
}

__global__ __launch_bounds__(256) void embed_kernel(
    const float* __restrict__ s,
    const float* __restrict__ W1, const float* __restrict__ b1,
    const float* __restrict__ W2, const float* __restrict__ b2)
{
    extern __shared__ uint32_t smem_u[];
    uint32_t* sS = smem_u;               // 128 x STR (tf32)
    uint32_t* sW = smem_u + 128 * STR;   // 128 x STR (tf32)

    const int t    = threadIdx.x;
    const int r0   = blockIdx.x * BM;
    const int wid  = t >> 5, lane = t & 31;
    const int wm   = wid & 1, wn = wid >> 1;
    const int gid  = lane >> 2, tig = lane & 3;

    // ---- load s tile [128 x 128] (guarded), convert to tf32 ----
#pragma unroll
    for (int i = 0; i < 16; i++) {
        int idx4 = t + i * 256;
        int row  = idx4 >> 5;
        int c4   = (idx4 & 31) * 4;
        float4 val = make_float4(0.f, 0.f, 0.f, 0.f);
        if (r0 + row < N_NODES)
            val = *(const float4*)(s + (size_t)(r0 + row) * H + c4);
        uint32_t* p = sS + row * STR + c4;
        p[0] = f2tf(val.x); p[1] = f2tf(val.y);
        p[2] = f2tf(val.z); p[3] = f2tf(val.w);
    }
    // ---- load W1 [128 x 128] ----
#pragma unroll
    for (int i = 0; i < 16; i++) {
        int idx4 = t + i * 256;
        int row  = idx4 >> 5;
        int c4   = (idx4 & 31) * 4;
        float4 val = *(const float4*)(W1 + (size_t)row * H + c4);
        uint32_t* p = sW + row * STR + c4;
        p[0] = f2tf(val.x); p[1] = f2tf(val.y);
        p[2] = f2tf(val.z); p[3] = f2tf(val.w);
    }
    __syncthreads();

    // ---- phase 1: acc = s @ W1 ----
    float acc[4][4][4];
#pragma unroll
    for (int mt = 0; mt < 4; mt++)
#pragma unroll
        for (int nt = 0; nt < 4; nt++)
#pragma unroll
            for (int i = 0; i < 4; i++) acc[mt][nt][i] = 0.f;

    compute_mma(acc, sS, sW, wm, wn, gid, tig);
    __syncthreads();

    // ---- h1 = tanh(acc + b1) back into sS as tf32 ----
#pragma unroll
    for (int mt = 0; mt < 4; mt++) {
        int row = wm * 64 + mt * 16 + gid;
#pragma unroll
        for (int nt = 0; nt < 4; nt++) {
            int col = wn * 32 + nt * 8 + tig * 2;
            float ba = __ldg(b1 + col), bb = __ldg(b1 + col + 1);
            sS[row * STR + col]           = f2tf(tanhf(acc[mt][nt][0] + ba));
            sS[row * STR + col + 1]       = f2tf(tanhf(acc[mt][nt][1] + bb));
            sS[(row + 8) * STR + col]     = f2tf(tanhf(acc[mt][nt][2] + ba));
            sS[(row + 8) * STR + col + 1] = f2tf(tanhf(acc[mt][nt][3] + bb));
        }
    }

    // ---- phase 2: s_exp = h1 @ W2 + b2, 3 chunks of 128 cols, store fp16 ----
    for (int chunk = 0; chunk < 3; chunk++) {
        __syncthreads();
#pragma unroll
        for (int i = 0; i < 16; i++) {
            int idx4 = t + i * 256;
            int row  = idx4 >> 5;
            int c4   = (idx4 & 31) * 4;
            float4 val = *(const float4*)(W2 + (size_t)row * H3
                                          + chunk * 128 + c4);
            uint32_t* p = sW + row * STR + c4;
            p[0] = f2tf(val.x); p[1] = f2tf(val.y);
            p[2] = f2tf(val.z); p[3] = f2tf(val.w);
        }
        __syncthreads();

        float acc2[4][4][4];
#pragma unroll
        for (int mt = 0; mt < 4; mt++)
#pragma unroll
            for (int nt = 0; nt < 4; nt++)
#pragma unroll
                for (int i = 0; i < 4; i++) acc2[mt][nt][i] = 0.f;

        compute_mma(acc2, sS, sW, wm, wn, gid, tig);

#pragma unroll
        for (int mt = 0; mt < 4; mt++) {
            int rl = wm * 64 + mt * 16 + gid;
#pragma unroll
            for (int nt = 0; nt < 4; nt++) {
                int col = chunk * 128 + wn * 32 + nt * 8 + tig * 2;
                float ba = __ldg(b2 + col), bb = __ldg(b2 + col + 1);
                int row = r0 + rl;
                if (row < N_NODES)
                    g_sexp16[(size_t)row * (H3 / 2) + (col >> 1)] =
                        __floats2half2_rn(acc2[mt][nt][0] + ba,
                                          acc2[mt][nt][1] + bb);
                if (row + 8 < N_NODES)
                    g_sexp16[(size_t)(row + 8) * (H3 / 2) + (col >> 1)] =
                        __floats2half2_rn(acc2[mt][nt][2] + ba,
                                          acc2[mt][nt][3] + bb);
            }
        }
    }
}

// ---------------------------------------------------------------------------
// v -> fp16 streaming conversion
// ---------------------------------------------------------------------------
__global__ __launch_bounds__(256) void vconv_kernel(const float* __restrict__ v) {
    size_t i = (size_t)blockIdx.x * 256 + threadIdx.x;
    const size_t n2 = (size_t)N_NODES * H3 / 2;
    if (i < n2) {
        float2 f = ((const float2*)v)[i];
        g_v16[i] = __floats2half2_rn(f.x, f.y);
    }
}

// ---------------------------------------------------------------------------
// CSR build: histogram -> single-block scan -> bucket fill (with payload)
// ---------------------------------------------------------------------------
__global__ __launch_bounds__(256) void hist_kernel(const int* __restrict__ ei) {
    int i = blockIdx.x * 256 + threadIdx.x;
    if (i < N_EDGES) atomicAdd(&g_count[__ldg(ei + N_EDGES + i)], 1);
}

__global__ __launch_bounds__(1024) void scan_kernel() {
    __shared__ int tmp[1024];
    const int per = (N_NODES + 1023) / 1024;
    const int t = threadIdx.x;
    const int base = t * per;
    int sum = 0;
    for (int i = 0; i < per; i++) {
        int idx = base + i;
        if (idx < N_NODES) sum += g_count[idx];
    }
    tmp[t] = sum;
    __syncthreads();
    for (int off = 1; off < 1024; off <<= 1) {
        int v = (t >= off) ? tmp[t - off] : 0;
        __syncthreads();
        tmp[t] += v;
        __syncthreads();
    }
    int run = tmp[t] - sum;
    for (int i = 0; i < per; i++) {
        int idx = base + i;
        if (idx < N_NODES) {
            g_start[idx] = run;
            run += g_count[idx];
        }
    }
    if (t == 0) g_start[N_NODES] = N_EDGES;
}

__global__ __launch_bounds__(256) void fill_kernel(
    const int* __restrict__ ei,
    const float* __restrict__ dij,
    const float* __restrict__ dir)
{
    int e = blockIdx.x * 256 + threadIdx.x;
    if (e >= N_EDGES) return;
    int dst = __ldg(ei + N_EDGES + e);
    int pos = g_start[dst] + atomicAdd(&g_fill[dst], 1);
    g_bsrc[pos] = __ldg(ei + e);
    g_bdat[pos] = make_float4(__ldg(dij + e), __ldg(dir + 3 * e),
                              __ldg(dir + 3 * e + 1), __ldg(dir + 3 * e + 2));
}

// ---------------------------------------------------------------------------
// Kernel 2: gather + finalize. 128-thread block = 2 nodes x 64 threads.
// Thread owns half2 column pair c (cols 2c, 2c+1). fp32 accumulate.
// ---------------------------------------------------------------------------
__global__ __launch_bounds__(128) void gather_kernel(
    const float* __restrict__ v,
    const float* __restrict__ s,
    const float* __restrict__ Wd,
    const float* __restrict__ bd,
    float* __restrict__ out)
{
    const int t    = threadIdx.x;
    const int node = blockIdx.x * 2 + (t >> 6);
    const int c    = t & 63;                 // half2 column index, 0..63

    const int beg = g_start[node];
    const int end = g_start[node + 1];

    const float2 wv = *(const float2*)(Wd + 2 * c);
    const float2 bv = *(const float2*)(bd + 2 * c);
    const float2 ws = *(const float2*)(Wd + 128 + 2 * c);
    const float2 bs = *(const float2*)(bd + 128 + 2 * c);
    const float2 wr = *(const float2*)(Wd + 256 + 2 * c);
    const float2 br = *(const float2*)(bd + 256 + 2 * c);

    float2 accs = make_float2(0.f, 0.f);
    float2 a0 = accs, a1 = accs, a2 = accs;

#pragma unroll 4
    for (int j = beg; j < end; j++) {
        const int src = __ldg(g_bsrc + j);
        const float4 ed = __ldg(g_bdat + j);    // {d, d0, d1, d2}

        const __half2* sx = g_sexp16 + (size_t)src * 192;
        const float2 ev = __half22float2(__ldg(sx + c));
        const float2 es = __half22float2(__ldg(sx + 64 + c));
        const float2 er = __half22float2(__ldg(sx + 128 + c));

        const float gvx = ev.x * fmaf(ed.x, wv.x, bv.x);
        const float gvy = ev.y * fmaf(ed.x, wv.y, bv.y);
        const float grx = er.x * fmaf(ed.x, wr.x, br.x);
        const float gry = er.y * fmaf(ed.x, wr.y, br.y);

        accs.x = fmaf(es.x, fmaf(ed.x, ws.x, bs.x), accs.x);
        accs.y = fmaf(es.y, fmaf(ed.x, ws.y, bs.y), accs.y);

        const __half2* vb = g_v16 + (size_t)src * 192;
        const float2 v0 = __half22float2(__ldg(vb + c));
        const float2 v1 = __half22float2(__ldg(vb + 64 + c));
        const float2 v2 = __half22float2(__ldg(vb + 128 + c));

        a0.x = fmaf(grx, ed.y, fmaf(gvx, v0.x, a0.x));
        a0.y = fmaf(gry, ed.y, fmaf(gvy, v0.y, a0.y));
        a1.x = fmaf(grx, ed.z, fmaf(gvx, v1.x, a1.x));
        a1.y = fmaf(gry, ed.z, fmaf(gvy, v1.y, a1.y));
        a2.x = fmaf(grx, ed.w, fmaf(gvx, v2.x, a2.x));
        a2.y = fmaf(gry, ed.w, fmaf(gvy, v2.y, a2.y));
    }

    const float inv = 1.0f / fmaxf((float)(end - beg), 1.0f);

    const size_t vb = (size_t)node * H3;
    float2 o;
    float2 x0 = *(const float2*)(v + vb + 2 * c);
    o = make_float2(fmaf(a0.x, inv, x0.x), fmaf(a0.y, inv, x0.y));
    *(float2*)(out + vb + 2 * c) = o;
    float2 x1 = *(const float2*)(v + vb + 128 + 2 * c);
    o = make_float2(fmaf(a1.x, inv, x1.x), fmaf(a1.y, inv, x1.y));
    *(float2*)(out + vb + 128 + 2 * c) = o;
    float2 x2 = *(const float2*)(v + vb + 256 + 2 * c);
    o = make_float2(fmaf(a2.x, inv, x2.x), fmaf(a2.y, inv, x2.y));
    *(float2*)(out + vb + 256 + 2 * c) = o;

    float2 xs = *(const float2*)(s + (size_t)node * H + 2 * c);
    o = make_float2(fmaf(accs.x, inv, xs.x), fmaf(accs.y, inv, xs.y));
    *(float2*)(out + (size_t)N_NODES * H3 + (size_t)node * H + 2 * c) = o;
}

// ---------------------------------------------------------------------------
extern "C" void kernel_launch(void* const* d_in, const int* in_sizes, int n_in,
                              void* d_out, int out_size) {
    const float* v   = (const float*)d_in[0];
    const float* s   = (const float*)d_in[1];
    const int*   ei  = (const int*)  d_in[2];
    const float* dij = (const float*)d_in[3];
    const float* dir = (const float*)d_in[4];
    const float* W1  = (const float*)d_in[5];
    const float* b1  = (const float*)d_in[6];
    const float* W2  = (const float*)d_in[7];
    const float* b2  = (const float*)d_in[8];
    const float* Wd  = (const float*)d_in[9];
    const float* bd  = (const float*)d_in[10];
    float* out = (float*)d_out;

    cudaFuncSetAttribute(embed_kernel,
                         cudaFuncAttributeMaxDynamicSharedMemorySize,
                         SMEM_EMBED_BYTES);

    void *pcnt, *pfill;
    cudaGetSymbolAddress(&pcnt,  g_count);
    cudaGetSymbolAddress(&pfill, g_fill);
    cudaMemsetAsync(pcnt,  0, sizeof(int) * N_NODES, 0);
    cudaMemsetAsync(pfill, 0, sizeof(int) * N_NODES, 0);

    embed_kernel<<<(N_NODES + BM - 1) / BM, 256, SMEM_EMBED_BYTES>>>(
        s, W1, b1, W2, b2);
    vconv_kernel<<<(int)(((size_t)N_NODES * H3 / 2 + 255) / 256), 256>>>(v);
    hist_kernel<<<(N_EDGES + 255) / 256, 256>>>(ei);
    scan_kernel<<<1, 1024>>>();
    fill_kernel<<<(N_EDGES + 255) / 256, 256>>>(ei, dij, dir);
    gather_kernel<<<N_NODES / 2, 128>>>(v, s, Wd, bd, out);
}

// round 6
// speedup vs baseline: 2.6647x; 1.1461x over previous
#include <cuda_runtime.h>
#include <cuda_fp16.h>
#include <cstdint>
#include <cstddef>

#define N_NODES 50000
#define N_EDGES 500000
#define H 128
#define H3 384
#define SCAN_B 256
#define N_SBLK ((N_NODES + SCAN_B - 1) / SCAN_B)   // 196

// ---------------- scratch (static device allocations, allowed) --------------
__device__ __half2 g_sexp16[(size_t)N_NODES * H3 / 2];  // 38.4 MB
__device__ __half2 g_v16  [(size_t)N_NODES * H3 / 2];   // 38.4 MB
__device__ int    g_count[N_NODES];
__device__ int    g_fill [N_NODES];
__device__ int    g_start[N_NODES + 1];
__device__ int    g_bsum [N_SBLK];
__device__ int    g_boff [N_SBLK];
__device__ int    g_bsrc [N_EDGES];                      // src per bucket slot
__device__ float4 g_bdat [N_EDGES];                      // {d, dir0, dir1, dir2}

// ---------------------------------------------------------------------------
// tf32 helpers (mma.sync m16n8k8, fp32 accumulate)
// ---------------------------------------------------------------------------
__device__ __forceinline__ uint32_t f2tf(float f) {
    uint32_t u;
    asm("cvt.rna.tf32.f32 %0, %1;" : "=r"(u) : "f"(f));
    return u;
}

__device__ __forceinline__ void mma_tf32(float c[4],
                                         uint32_t a0, uint32_t a1,
                                         uint32_t a2, uint32_t a3,
                                         uint32_t b0, uint32_t b1) {
    asm volatile(
        "mma.sync.aligned.m16n8k8.row.col.f32.tf32.tf32.f32 "
        "{%0,%1,%2,%3}, {%4,%5,%6,%7}, {%8,%9}, {%0,%1,%2,%3};"
        : "+f"(c[0]), "+f"(c[1]), "+f"(c[2]), "+f"(c[3])
        : "r"(a0), "r"(a1), "r"(a2), "r"(a3), "r"(b0), "r"(b1));
}

// ---------------------------------------------------------------------------
// Kernel 1: s_exp = tanh(s @ W1 + b1) @ W2 + b2   -> fp16 g_sexp16  [N, 384]
// Block: 128 rows, 256 threads (8 warps). Warp: 64x32 via 4x4 m16n8k8 tiles.
// ---------------------------------------------------------------------------
#define BM 128
#define STR 132
#define SMEM_EMBED_BYTES (2 * 128 * STR * 4)

__device__ __forceinline__ void compute_mma(float acc[4][4][4],
                                            const uint32_t* __restrict__ sA,
                                            const uint32_t* __restrict__ sW,
                                            int wm, int wn, int gid, int tig) {
#pragma unroll
    for (int k = 0; k < 128; k += 8) {
        uint32_t a[4][4];
#pragma unroll
        for (int mt = 0; mt < 4; mt++) {
            int r = wm * 64 + mt * 16 + gid;
            a[mt][0] = sA[r * STR + k + tig];
            a[mt][1] = sA[(r + 8) * STR + k + tig];
            a[mt][2] = sA[r * STR + k + tig + 4];
            a[mt][3] = sA[(r + 8) * STR + k + tig + 4];
        }
#pragma unroll
        for (int nt = 0; nt < 4; nt++) {
            int ncol = wn * 32 + nt * 8 + gid;
            uint32_t b0 = sW[(k + tig) * STR + ncol];
            uint32_t b1 = sW[(k + tig + 4) * STR + ncol];
#pragma unroll
            for (int mt = 0; mt < 4; mt++)
                mma_tf32(acc[mt][nt], a[mt][0], a[mt][1], a[mt][2], a[mt][3],
                         b0, b1);
        }
    }
}

__global__ __launch_bounds__(256) void embed_kernel(
    const float* __restrict__ s,
    const float* __restrict__ W1, const float* __restrict__ b1,
    const float* __restrict__ W2, const float* __restrict__ b2)
{
    extern __shared__ uint32_t smem_u[];
    uint32_t* sS = smem_u;               // 128 x STR (tf32)
    uint32_t* sW = smem_u + 128 * STR;   // 128 x STR (tf32)

    const int t    = threadIdx.x;
    const int r0   = blockIdx.x * BM;
    const int wid  = t >> 5, lane = t & 31;
    const int wm   = wid & 1, wn = wid >> 1;
    const int gid  = lane >> 2, tig = lane & 3;

    // ---- load s tile [128 x 128] (guarded), convert to tf32 ----
#pragma unroll
    for (int i = 0; i < 16; i++) {
        int idx4 = t + i * 256;
        int row  = idx4 >> 5;
        int c4   = (idx4 & 31) * 4;
        float4 val = make_float4(0.f, 0.f, 0.f, 0.f);
        if (r0 + row < N_NODES)
            val = *(const float4*)(s + (size_t)(r0 + row) * H + c4);
        uint32_t* p = sS + row * STR + c4;
        p[0] = f2tf(val.x); p[1] = f2tf(val.y);
        p[2] = f2tf(val.z); p[3] = f2tf(val.w);
    }
    // ---- load W1 [128 x 128] ----
#pragma unroll
    for (int i = 0; i < 16; i++) {
        int idx4 = t + i * 256;
        int row  = idx4 >> 5;
        int c4   = (idx4 & 31) * 4;
        float4 val = *(const float4*)(W1 + (size_t)row * H + c4);
        uint32_t* p = sW + row * STR + c4;
        p[0] = f2tf(val.x); p[1] = f2tf(val.y);
        p[2] = f2tf(val.z); p[3] = f2tf(val.w);
    }
    __syncthreads();

    // ---- phase 1: acc = s @ W1 ----
    float acc[4][4][4];
#pragma unroll
    for (int mt = 0; mt < 4; mt++)
#pragma unroll
        for (int nt = 0; nt < 4; nt++)
#pragma unroll
            for (int i = 0; i < 4; i++) acc[mt][nt][i] = 0.f;

    compute_mma(acc, sS, sW, wm, wn, gid, tig);
    __syncthreads();

    // ---- h1 = tanh(acc + b1) back into sS as tf32 ----
#pragma unroll
    for (int mt = 0; mt < 4; mt++) {
        int row = wm * 64 + mt * 16 + gid;
#pragma unroll
        for (int nt = 0; nt < 4; nt++) {
            int col = wn * 32 + nt * 8 + tig * 2;
            float ba = __ldg(b1 + col), bb = __ldg(b1 + col + 1);
            sS[row * STR + col]           = f2tf(tanhf(acc[mt][nt][0] + ba));
            sS[row * STR + col + 1]       = f2tf(tanhf(acc[mt][nt][1] + bb));
            sS[(row + 8) * STR + col]     = f2tf(tanhf(acc[mt][nt][2] + ba));
            sS[(row + 8) * STR + col + 1] = f2tf(tanhf(acc[mt][nt][3] + bb));
        }
    }

    // ---- phase 2: s_exp = h1 @ W2 + b2, 3 chunks of 128 cols, store fp16 ----
    for (int chunk = 0; chunk < 3; chunk++) {
        __syncthreads();
#pragma unroll
        for (int i = 0; i < 16; i++) {
            int idx4 = t + i * 256;
            int row  = idx4 >> 5;
            int c4   = (idx4 & 31) * 4;
            float4 val = *(const float4*)(W2 + (size_t)row * H3
                                          + chunk * 128 + c4);
            uint32_t* p = sW + row * STR + c4;
            p[0] = f2tf(val.x); p[1] = f2tf(val.y);
            p[2] = f2tf(val.z); p[3] = f2tf(val.w);
        }
        __syncthreads();

        float acc2[4][4][4];
#pragma unroll
        for (int mt = 0; mt < 4; mt++)
#pragma unroll
            for (int nt = 0; nt < 4; nt++)
#pragma unroll
                for (int i = 0; i < 4; i++) acc2[mt][nt][i] = 0.f;

        compute_mma(acc2, sS, sW, wm, wn, gid, tig);

#pragma unroll
        for (int mt = 0; mt < 4; mt++) {
            int rl = wm * 64 + mt * 16 + gid;
#pragma unroll
            for (int nt = 0; nt < 4; nt++) {
                int col = chunk * 128 + wn * 32 + nt * 8 + tig * 2;
                float ba = __ldg(b2 + col), bb = __ldg(b2 + col + 1);
                int row = r0 + rl;
                if (row < N_NODES)
                    g_sexp16[(size_t)row * (H3 / 2) + (col >> 1)] =
                        __floats2half2_rn(acc2[mt][nt][0] + ba,
                                          acc2[mt][nt][1] + bb);
                if (row + 8 < N_NODES)
                    g_sexp16[(size_t)(row + 8) * (H3 / 2) + (col >> 1)] =
                        __floats2half2_rn(acc2[mt][nt][2] + ba,
                                          acc2[mt][nt][3] + bb);
            }
        }
    }
}

// ---------------------------------------------------------------------------
// v -> fp16 streaming conversion
// ---------------------------------------------------------------------------
__global__ __launch_bounds__(256) void vconv_kernel(const float* __restrict__ v) {
    size_t i = (size_t)blockIdx.x * 256 + threadIdx.x;
    const size_t n2 = (size_t)N_NODES * H3 / 2;
    if (i < n2) {
        float2 f = ((const float2*)v)[i];
        g_v16[i] = __floats2half2_rn(f.x, f.y);
    }
}

// ---------------------------------------------------------------------------
// CSR build: histogram -> two-level scan -> bucket fill (with payload)
// ---------------------------------------------------------------------------
__global__ __launch_bounds__(256) void hist_kernel(const int* __restrict__ ei) {
    int i = blockIdx.x * 256 + threadIdx.x;
    if (i < N_EDGES) atomicAdd(&g_count[__ldg(ei + N_EDGES + i)], 1);
}

// per-block sums of 256 counts
__global__ __launch_bounds__(SCAN_B) void scan1_kernel() {
    __shared__ int red[SCAN_B / 32];
    const int idx = blockIdx.x * SCAN_B + threadIdx.x;
    int val = (idx < N_NODES) ? g_count[idx] : 0;
#pragma unroll
    for (int o = 16; o > 0; o >>= 1)
        val += __shfl_down_sync(0xffffffffu, val, o);
    if ((threadIdx.x & 31) == 0) red[threadIdx.x >> 5] = val;
    __syncthreads();
    if (threadIdx.x < SCAN_B / 32) {
        int v = red[threadIdx.x];
#pragma unroll
        for (int o = SCAN_B / 64; o > 0; o >>= 1)
            v += __shfl_down_sync(0xffu, v, o);
        if (threadIdx.x == 0) g_bsum[blockIdx.x] = v;
    }
}

// single small block: exclusive scan of N_SBLK partials
__global__ __launch_bounds__(256) void scan2_kernel() {
    __shared__ int tmp[256];
    const int t = threadIdx.x;
    int v = (t < N_SBLK) ? g_bsum[t] : 0;
    tmp[t] = v;
    __syncthreads();
#pragma unroll
    for (int off = 1; off < 256; off <<= 1) {
        int u = (t >= off) ? tmp[t - off] : 0;
        __syncthreads();
        tmp[t] += u;
        __syncthreads();
    }
    if (t < N_SBLK) g_boff[t] = tmp[t] - v;   // exclusive
    if (t == 0) g_start[N_NODES] = N_EDGES;
}

// per-block local exclusive scan + block offset -> g_start
__global__ __launch_bounds__(SCAN_B) void scan3_kernel() {
    __shared__ int tmp[SCAN_B];
    const int t = threadIdx.x;
    const int idx = blockIdx.x * SCAN_B + t;
    int v = (idx < N_NODES) ? g_count[idx] : 0;
    tmp[t] = v;
    __syncthreads();
#pragma unroll
    for (int off = 1; off < SCAN_B; off <<= 1) {
        int u = (t >= off) ? tmp[t - off] : 0;
        __syncthreads();
        tmp[t] += u;
        __syncthreads();
    }
    if (idx < N_NODES)
        g_start[idx] = g_boff[blockIdx.x] + tmp[t] - v;
}

__global__ __launch_bounds__(256) void fill_kernel(
    const int* __restrict__ ei,
    const float* __restrict__ dij,
    const float* __restrict__ dir)
{
    int e = blockIdx.x * 256 + threadIdx.x;
    if (e >= N_EDGES) return;
    int dst = __ldg(ei + N_EDGES + e);
    int pos = g_start[dst] + atomicAdd(&g_fill[dst], 1);
    g_bsrc[pos] = __ldg(ei + e);
    g_bdat[pos] = make_float4(__ldg(dij + e), __ldg(dir + 3 * e),
                              __ldg(dir + 3 * e + 1), __ldg(dir + 3 * e + 2));
}

// ---------------------------------------------------------------------------
// Kernel 2: gather + finalize. 128-thread block = 2 nodes x 64 threads.
// Thread owns half2 column pair c (cols 2c, 2c+1). fp32 accumulate.
// ---------------------------------------------------------------------------
__global__ __launch_bounds__(128) void gather_kernel(
    const float* __restrict__ v,
    const float* __restrict__ s,
    const float* __restrict__ Wd,
    const float* __restrict__ bd,
    float* __restrict__ out)
{
    const int t    = threadIdx.x;
    const int node = blockIdx.x * 2 + (t >> 6);
    const int c    = t & 63;                 // half2 column index, 0..63

    const int beg = g_start[node];
    const int end = g_start[node + 1];

    const float2 wv = *(const float2*)(Wd + 2 * c);
    const float2 bv = *(const float2*)(bd + 2 * c);
    const float2 ws = *(const float2*)(Wd + 128 + 2 * c);
    const float2 bs = *(const float2*)(bd + 128 + 2 * c);
    const float2 wr = *(const float2*)(Wd + 256 + 2 * c);
    const float2 br = *(const float2*)(bd + 256 + 2 * c);

    float2 accs = make_float2(0.f, 0.f);
    float2 a0 = accs, a1 = accs, a2 = accs;

#pragma unroll 4
    for (int j = beg; j < end; j++) {
        const int src = __ldg(g_bsrc + j);
        const float4 ed = __ldg(g_bdat + j);    // {d, d0, d1, d2}

        const __half2* sx = g_sexp16 + (size_t)src * 192;
        const float2 ev = __half22float2(__ldg(sx + c));
        const float2 es = __half22float2(__ldg(sx + 64 + c));
        const float2 er = __half22float2(__ldg(sx + 128 + c));

        const float gvx = ev.x * fmaf(ed.x, wv.x, bv.x);
        const float gvy = ev.y * fmaf(ed.x, wv.y, bv.y);
        const float grx = er.x * fmaf(ed.x, wr.x, br.x);
        const float gry = er.y * fmaf(ed.x, wr.y, br.y);

        accs.x = fmaf(es.x, fmaf(ed.x, ws.x, bs.x), accs.x);
        accs.y = fmaf(es.y, fmaf(ed.x, ws.y, bs.y), accs.y);

        const __half2* vb = g_v16 + (size_t)src * 192;
        const float2 v0 = __half22float2(__ldg(vb + c));
        const float2 v1 = __half22float2(__ldg(vb + 64 + c));
        const float2 v2 = __half22float2(__ldg(vb + 128 + c));

        a0.x = fmaf(grx, ed.y, fmaf(gvx, v0.x, a0.x));
        a0.y = fmaf(gry, ed.y, fmaf(gvy, v0.y, a0.y));
        a1.x = fmaf(grx, ed.z, fmaf(gvx, v1.x, a1.x));
        a1.y = fmaf(gry, ed.z, fmaf(gvy, v1.y, a1.y));
        a2.x = fmaf(grx, ed.w, fmaf(gvx, v2.x, a2.x));
        a2.y = fmaf(gry, ed.w, fmaf(gvy, v2.y, a2.y));
    }

    const float inv = 1.0f / fmaxf((float)(end - beg), 1.0f);

    const size_t vb = (size_t)node * H3;
    float2 o;
    float2 x0 = *(const float2*)(v + vb + 2 * c);
    o = make_float2(fmaf(a0.x, inv, x0.x), fmaf(a0.y, inv, x0.y));
    *(float2*)(out + vb + 2 * c) = o;
    float2 x1 = *(const float2*)(v + vb + 128 + 2 * c);
    o = make_float2(fmaf(a1.x, inv, x1.x), fmaf(a1.y, inv, x1.y));
    *(float2*)(out + vb + 128 + 2 * c) = o;
    float2 x2 = *(const float2*)(v + vb + 256 + 2 * c);
    o = make_float2(fmaf(a2.x, inv, x2.x), fmaf(a2.y, inv, x2.y));
    *(float2*)(out + vb + 256 + 2 * c) = o;

    float2 xs = *(const float2*)(s + (size_t)node * H + 2 * c);
    o = make_float2(fmaf(accs.x, inv, xs.x), fmaf(accs.y, inv, xs.y));
    *(float2*)(out + (size_t)N_NODES * H3 + (size_t)node * H + 2 * c) = o;
}

// ---------------------------------------------------------------------------
extern "C" void kernel_launch(void* const* d_in, const int* in_sizes, int n_in,
                              void* d_out, int out_size) {
    const float* v   = (const float*)d_in[0];
    const float* s   = (const float*)d_in[1];
    const int*   ei  = (const int*)  d_in[2];
    const float* dij = (const float*)d_in[3];
    const float* dir = (const float*)d_in[4];
    const float* W1  = (const float*)d_in[5];
    const float* b1  = (const float*)d_in[6];
    const float* W2  = (const float*)d_in[7];
    const float* b2  = (const float*)d_in[8];
    const float* Wd  = (const float*)d_in[9];
    const float* bd  = (const float*)d_in[10];
    float* out = (float*)d_out;

    cudaFuncSetAttribute(embed_kernel,
                         cudaFuncAttributeMaxDynamicSharedMemorySize,
                         SMEM_EMBED_BYTES);

    void *pcnt, *pfill;
    cudaGetSymbolAddress(&pcnt,  g_count);
    cudaGetSymbolAddress(&pfill, g_fill);
    cudaMemsetAsync(pcnt,  0, sizeof(int) * N_NODES, 0);
    cudaMemsetAsync(pfill, 0, sizeof(int) * N_NODES, 0);

    embed_kernel<<<(N_NODES + BM - 1) / BM, 256, SMEM_EMBED_BYTES>>>(
        s, W1, b1, W2, b2);
    vconv_kernel<<<(int)(((size_t)N_NODES * H3 / 2 + 255) / 256), 256>>>(v);
    hist_kernel<<<(N_EDGES + 255) / 256, 256>>>(ei);
    scan1_kernel<<<N_SBLK, SCAN_B>>>();
    scan2_kernel<<<1, 256>>>();
    scan3_kernel<<<N_SBLK, SCAN_B>>>();
    fill_kernel<<<(N_EDGES + 255) / 256, 256>>>(ei, dij, dir);
    gather_kernel<<<N_NODES / 2, 128>>>(v, s, Wd, bd, out);
}